// round 10
// baseline (speedup 1.0000x reference)
#include <cuda_runtime.h>
#include <math.h>
#include <stdint.h>

// Problem shapes (fixed by the dataset)
#define Bv   32
#define Sv   4096
#define BSv  (Bv * Sv)      // 131072 rows
#define Dv   768            // K
#define Hv   1024           // N

#define BMt  128            // CTA M tile
#define BNt  256            // CTA N tile
#define NTt  (Hv / BNt)     // 4 N-tiles
#define NCH  (Dv / 32)      // 24 k-chunks of 32

// smem layout (floats)
#define A_BUF   8192        // one A buffer: 2 splits x 8 mblk x 4 ks x 32 pos x 4
#define B_BUF   16384       // one B buffer: 2 splits x 32 nblk x 2 ksp x 32 pos x 4
#define OFF_A   0
#define OFF_B   16384
#define OFF_SHB 49152
#define OFF_SW2 49408
#define OFF_RED 49664
#define SMEM_FLOATS 50176
#define SMEM_BYTES  (SMEM_FLOATS * 4)   // 200704

// ---------------- scratch (static device globals; no allocation) ----------
__device__ float g_mu[BSv];
__device__ float g_rstd[BSv];
__device__ float g_scores[BSv];
__device__ float g_part[NTt * BSv];
// W pre-split into 2 tf32 parts, stored FRAGMENT-MAJOR:
// [split][kchunk 24][nblk 128][ksp 2][slot 32][4 floats]
__device__ __align__(16) float g_Wf[2 * 24 * 128 * 2 * 32 * 4];
__device__ float g_hbias[Hv];

// ---------------- helpers ---------------------------------------------------
__device__ __forceinline__ float tf32_hi(float x) {
    uint32_t r;
    asm("cvt.rna.tf32.f32 %0, %1;" : "=r"(r) : "f"(x));
    return __uint_as_float(r);
}
#define MMA_TF32(c, a, b)                                                    \
    asm volatile("mma.sync.aligned.m16n8k8.row.col.f32.tf32.tf32.f32 "      \
                 "{%0,%1,%2,%3}, {%4,%5,%6,%7}, {%8,%9}, {%0,%1,%2,%3};"    \
                 : "+f"((c)[0]), "+f"((c)[1]), "+f"((c)[2]), "+f"((c)[3])   \
                 : "r"((a)[0]), "r"((a)[1]), "r"((a)[2]), "r"((a)[3]),      \
                   "r"((b)[0]), "r"((b)[1]))

__device__ __forceinline__ float gelu_exact(float x) {
    return 0.5f * x * (1.0f + erff(x * 0.7071067811865475f));
}
__device__ __forceinline__ float softplusf(float x) {
    return fmaxf(x, 0.0f) + log1pf(expf(-fabsf(x)));
}

// ---------------- prep: fold ln_g into W1, split, write frag-major --------
__global__ void split_w_frag(const float* __restrict__ w1, const float* __restrict__ lng) {
    int i = blockIdx.x * 256 + threadIdx.x;     // i < Hv*Dv
    int n = i / Dv, k = i % Dv;
    float w = w1[i] * lng[k];
    float w1f = tf32_hi(w);
    float w2f = tf32_hi(w - w1f);
    int kc = k >> 5, kl = k & 31;
    int ksp = kl >> 4, klp = kl & 15;
    int ks1 = klp >> 3, k4 = (klp >> 2) & 1, tg = klp & 3;
    int comp = ks1 * 2 + k4;
    int nblk = n >> 3, gg = n & 7;
    int slot = tg * 8 + gg;
    size_t G0 = ((((size_t)0 * 24 + kc) * 128 + nblk) * 2 + ksp) * 32 + slot;
    size_t G1 = ((((size_t)1 * 24 + kc) * 128 + nblk) * 2 + ksp) * 32 + slot;
    g_Wf[G0 * 4 + comp] = w1f;
    g_Wf[G1 * 4 + comp] = w2f;
}

__global__ void prep_hbias(const float* __restrict__ w1, const float* __restrict__ lnb,
                           const float* __restrict__ b1) {
    int h    = blockIdx.x * 8 + (threadIdx.x >> 5);
    int lane = threadIdx.x & 31;
    const float* wr = w1 + (size_t)h * Dv;
    float s = 0.0f;
    for (int d = lane; d < Dv; d += 32) s = fmaf(lnb[d], wr[d], s);
#pragma unroll
    for (int o = 16; o; o >>= 1) s += __shfl_xor_sync(0xffffffffu, s, o);
    if (lane == 0) g_hbias[h] = s + b1[h];
}

// ---------------- LayerNorm stats: one warp per row -----------------------
__global__ void ln_stats(const float* __restrict__ emb, const float* __restrict__ attn) {
    int row  = blockIdx.x * 8 + (threadIdx.x >> 5);
    int lane = threadIdx.x & 31;
    const float4* ev = (const float4*)(emb + (size_t)row * Dv);
    float at = attn[row];
    float s = 0.0f, ss = 0.0f;
#pragma unroll
    for (int j = 0; j < Dv / 128; j++) {
        float4 v = ev[lane + 32 * j];
        float a = v.x * at, b = v.y * at, c = v.z * at, d = v.w * at;
        s += a + b + c + d;
        ss = fmaf(a, a, ss); ss = fmaf(b, b, ss);
        ss = fmaf(c, c, ss); ss = fmaf(d, d, ss);
    }
#pragma unroll
    for (int o = 16; o; o >>= 1) {
        s  += __shfl_xor_sync(0xffffffffu, s,  o);
        ss += __shfl_xor_sync(0xffffffffu, ss, o);
    }
    if (lane == 0) {
        float mu  = s * (1.0f / Dv);
        float var = fmaxf(ss * (1.0f / Dv) - mu * mu, 0.0f);
        g_mu[row]   = mu;
        g_rstd[row] = 1.0f / sqrtf(var + 1e-5f);
    }
}

// ---------------- fused LN + 3xTF32 GEMM + GELU + w2-dot ------------------
// CTA 128x256, 8 warps (2x4), warp tile 64x64. Fragment-major smem:
//   A[buf][split][mblk 8][ks 4][pos 32]{a0,a2,a1,a3}  (producer STS.64, LN+split on the fly)
//   B[buf][split][nblk 32][ksp 2][pos 32]{b0,b1 ks1=0; b0,b1 ks1=1}  (cp.async from g_Wf)
// Consumer: A = 1 LDS.128 per (split,tm); B = 1 LDS.64 per (split,tn).

__global__ void __launch_bounds__(256, 1)
gemm_tf32(const float* __restrict__ emb, const float* __restrict__ attn,
          const float* __restrict__ w2) {
    extern __shared__ float smf[];
    uint32_t smemB_u32 = (uint32_t)__cvta_generic_to_shared(&smf[OFF_B]);

    int nt = blockIdx.x, mt = blockIdx.y;
    int m0 = mt * BMt;
    int tid = threadIdx.x;
    int lane = tid & 31, wid = tid >> 5;
    int warp_m = wid >> 2, warp_n = wid & 3;          // 2 x 4
    int g = lane >> 2, tig = lane & 3;
    int pc = tig * 8 + g;                              // fragment position

    // stage hbias, w2 (this CTA's 256 cols)
    smf[OFF_SHB + tid] = g_hbias[nt * BNt + tid];
    smf[OFF_SW2 + tid] = w2[nt * BNt + tid];

    // A producer row constants
    int mrow = m0 + (tid & 127);
    int hA = tid >> 7;                                 // k-half (16 k each)
    float rsv = g_rstd[mrow];
    float sA = attn[mrow] * rsv;
    float tA = g_mu[mrow] * rsv;
    int mm = tid & 127;
    int gA = mm & 7, hiA = (mm >> 3) & 1, mblkA = mm >> 4;

// One B buffer = 4096 x 16B lines; 256 threads -> 16 lines per thread.
#define PRODUCE_B(KC, BUF)                                                      \
    do {                                                                        \
        _Pragma("unroll")                                                       \
        for (int i_ = 0; i_ < 16; i_++) {                                       \
            int L_ = i_ * 256 + tid;                                            \
            int slot_ = L_ & 31, ksp_ = (L_ >> 5) & 1;                          \
            int nbl_ = (L_ >> 6) & 31, sp_ = L_ >> 11;                          \
            size_t G_ = ((((size_t)sp_ * 24 + (KC)) * 128 + nt * 32 + nbl_) * 2 \
                         + ksp_) * 32 + slot_;                                  \
            uint32_t sa_ = smemB_u32 + (uint32_t)((BUF) * (B_BUF * 4) + L_ * 16);\
            const float* gp_ = g_Wf + G_ * 4;                                   \
            asm volatile("cp.async.cg.shared.global [%0], [%1], 16;"            \
                         :: "r"(sa_), "l"(gp_) : "memory");                     \
        }                                                                       \
        asm volatile("cp.async.commit_group;" ::: "memory");                    \
    } while (0)

#define PRODUCE_A(KC, BUF)                                                      \
    do {                                                                        \
        const float4* ea_ = (const float4*)(emb + (size_t)mrow * Dv             \
                                            + (KC) * 32 + hA * 16);             \
        float4 q0_ = ea_[0], q1_ = ea_[1], q2_ = ea_[2], q3_ = ea_[3];          \
        float v_[16] = {q0_.x, q0_.y, q0_.z, q0_.w, q1_.x, q1_.y, q1_.z, q1_.w, \
                        q2_.x, q2_.y, q2_.z, q2_.w, q3_.x, q3_.y, q3_.z, q3_.w};\
        _Pragma("unroll")                                                       \
        for (int sl_ = 0; sl_ < 2; sl_++) {                                     \
            int ks_ = 2 * hA + sl_;                                             \
            _Pragma("unroll")                                                   \
            for (int tg_ = 0; tg_ < 4; tg_++) {                                 \
                float xa_ = fmaf(v_[sl_ * 8 + tg_], sA, -tA);                   \
                float xb_ = fmaf(v_[sl_ * 8 + tg_ + 4], sA, -tA);               \
                float x1a_ = tf32_hi(xa_), x1b_ = tf32_hi(xb_);                 \
                float x2a_ = tf32_hi(xa_ - x1a_), x2b_ = tf32_hi(xb_ - x1b_);   \
                int p_ = tg_ * 8 + gA;                                          \
                int base_ = OFF_A + (BUF) * A_BUF + (mblkA * 4 + ks_) * 128     \
                            + p_ * 4 + hiA * 2;                                 \
                *(float2*)&smf[base_]        = make_float2(x1a_, x1b_);         \
                *(float2*)&smf[base_ + 4096] = make_float2(x2a_, x2b_);         \
            }                                                                   \
        }                                                                       \
    } while (0)

    float acc[4][8][4];
#pragma unroll
    for (int tm = 0; tm < 4; tm++)
#pragma unroll
        for (int tn = 0; tn < 8; tn++)
#pragma unroll
            for (int e = 0; e < 4; e++) acc[tm][tn][e] = 0.0f;

    // prologue
    PRODUCE_B(0, 0);
    PRODUCE_A(0, 0);
    asm volatile("cp.async.wait_group 0;" ::: "memory");
    __syncthreads();

    int st = 0;
#pragma unroll 1
    for (int c = 0; c < NCH; c++) {
        if (c + 1 < NCH) {
            PRODUCE_B(c + 1, st ^ 1);
            PRODUCE_A(c + 1, st ^ 1);
        }

        int aoff = OFF_A + st * A_BUF;
        int boff = OFF_B + st * B_BUF;
#pragma unroll 1
        for (int ksp = 0; ksp < 2; ksp++) {
#pragma unroll
            for (int ks1 = 0; ks1 < 2; ks1++) {
                int ks = ksp * 2 + ks1;
                uint32_t bf[2][8][2];
#pragma unroll
                for (int sp = 0; sp < 2; sp++)
#pragma unroll
                    for (int tn = 0; tn < 8; tn++) {
                        int nblk = warp_n * 8 + tn;
                        float2 bv = *(const float2*)&smf[boff
                            + ((sp * 32 + nblk) * 2 + ksp) * 128 + pc * 4 + ks1 * 2];
                        bf[sp][tn][0] = __float_as_uint(bv.x);
                        bf[sp][tn][1] = __float_as_uint(bv.y);
                    }
                uint32_t af[2][4][4];
#pragma unroll
                for (int sp = 0; sp < 2; sp++)
#pragma unroll
                    for (int tm = 0; tm < 4; tm++) {
                        int mblk = warp_m * 4 + tm;
                        float4 av = *(const float4*)&smf[aoff
                            + ((sp * 8 + mblk) * 4 + ks) * 128 + pc * 4];
                        af[sp][tm][0] = __float_as_uint(av.x);
                        af[sp][tm][1] = __float_as_uint(av.z);
                        af[sp][tm][2] = __float_as_uint(av.y);
                        af[sp][tm][3] = __float_as_uint(av.w);
                    }
#pragma unroll
                for (int tm = 0; tm < 4; tm++)
#pragma unroll
                    for (int tn = 0; tn < 8; tn++) {
                        MMA_TF32(acc[tm][tn], af[0][tm], bf[0][tn]);
                        MMA_TF32(acc[tm][tn], af[0][tm], bf[1][tn]);
                        MMA_TF32(acc[tm][tn], af[1][tm], bf[0][tn]);
                    }
            }
        }

        asm volatile("cp.async.wait_group 0;" ::: "memory");
        __syncthreads();
        st ^= 1;
    }

    // ---------------- epilogue: gelu(c + hbias) * w2, reduce ---------------
    float* shb = &smf[OFF_SHB];
    float* sw2 = &smf[OFF_SW2];
    float* red = &smf[OFF_RED];
#pragma unroll
    for (int tm = 0; tm < 4; tm++) {
        float rs0 = 0.0f, rs1 = 0.0f;
#pragma unroll
        for (int tn = 0; tn < 8; tn++) {
            int cl = warp_n * 64 + tn * 8 + 2 * tig;
            float h0 = shb[cl], h1 = shb[cl + 1];
            float w0 = sw2[cl], w1v = sw2[cl + 1];
            rs0 += gelu_exact(acc[tm][tn][0] + h0) * w0
                 + gelu_exact(acc[tm][tn][1] + h1) * w1v;
            rs1 += gelu_exact(acc[tm][tn][2] + h0) * w0
                 + gelu_exact(acc[tm][tn][3] + h1) * w1v;
        }
        rs0 += __shfl_xor_sync(0xffffffffu, rs0, 1);
        rs0 += __shfl_xor_sync(0xffffffffu, rs0, 2);
        rs1 += __shfl_xor_sync(0xffffffffu, rs1, 1);
        rs1 += __shfl_xor_sync(0xffffffffu, rs1, 2);
        if (tig == 0) {
            int r0 = warp_m * 64 + tm * 16 + g;
            red[r0 * 4 + warp_n]       = rs0;
            red[(r0 + 8) * 4 + warp_n] = rs1;
        }
    }
    __syncthreads();
    if (tid < BMt) {
        float p = red[tid * 4] + red[tid * 4 + 1] + red[tid * 4 + 2] + red[tid * 4 + 3];
        g_part[nt * BSv + m0 + tid] = p;
    }
}

// ---------------- fixed-order partial reduction (deterministic) -----------
__global__ void score_reduce() {
    int i = blockIdx.x * 256 + threadIdx.x;
    float s = 0.0f;
#pragma unroll
    for (int nt = 0; nt < NTt; nt++) s += g_part[nt * BSv + i];
    g_scores[i] = s;
}

// ---------------- entmax-1.5 over S via bisection on tau ------------------
__global__ void __launch_bounds__(1024)
entmax_kernel(const float* __restrict__ attn, const float* __restrict__ b2,
              float* __restrict__ zout) {
    __shared__ float sx[Sv];
    __shared__ float red[33];
    int b = blockIdx.x, tid = threadIdx.x;
    int lane = tid & 31, wid = tid >> 5;
    float b2v = b2[0];
    const float* sc = g_scores + (size_t)b * Sv;
    const float* at = attn + (size_t)b * Sv;

    float loc[4], am[4];
    float mx = -3.4e38f;
#pragma unroll
    for (int j = 0; j < 4; j++) {
        int i = tid + j * 1024;
        float a = at[i]; am[j] = a;
        float v = (a == 0.0f) ? -1e9f : sc[i] + b2v;
        v *= 0.5f;
        loc[j] = v;
        mx = fmaxf(mx, v);
    }
#pragma unroll
    for (int o = 16; o; o >>= 1) mx = fmaxf(mx, __shfl_xor_sync(0xffffffffu, mx, o));
    if (lane == 0) red[wid] = mx;
    __syncthreads();
    if (wid == 0) {
        float m = red[lane];
#pragma unroll
        for (int o = 16; o; o >>= 1) m = fmaxf(m, __shfl_xor_sync(0xffffffffu, m, o));
        if (lane == 0) red[32] = m;
    }
    __syncthreads();
    float xmax = red[32];
#pragma unroll
    for (int j = 0; j < 4; j++) sx[tid + j * 1024] = loc[j] - xmax;
    __syncthreads();

    float lo = -1.0f, hi = 0.0f;
    for (int it = 0; it < 30; it++) {
        float mid = 0.5f * (lo + hi);
        float s = 0.0f;
#pragma unroll
        for (int j = 0; j < 4; j++) {
            float d = fmaxf(sx[tid + j * 1024] - mid, 0.0f);
            s = fmaf(d, d, s);
        }
#pragma unroll
        for (int o = 16; o; o >>= 1) s += __shfl_xor_sync(0xffffffffu, s, o);
        __syncthreads();
        if (lane == 0) red[wid] = s;
        __syncthreads();
        if (wid == 0) {
            float t = red[lane];
#pragma unroll
            for (int o = 16; o; o >>= 1) t += __shfl_xor_sync(0xffffffffu, t, o);
            if (lane == 0) red[32] = t;
        }
        __syncthreads();
        float tot = red[32];
        if (tot >= 1.0f) lo = mid; else hi = mid;
    }
    float tau = 0.5f * (lo + hi);
#pragma unroll
    for (int j = 0; j < 4; j++) {
        int i = tid + j * 1024;
        float d = fmaxf(sx[i] - tau, 0.0f);
        zout[(size_t)b * Sv + i] = d * d * am[j];
    }
}

// ---------------- Kumaraswamy gate (g == h numerically) -------------------
__global__ void final_kernel(const float* __restrict__ attn, const float* __restrict__ u,
                             const float* __restrict__ b2, float* __restrict__ out,
                             int out_size) {
    int i = blockIdx.x * 256 + threadIdx.x;
    float a_ = attn[i];
    float sc = (a_ == 0.0f) ? -1e9f : g_scores[i] + b2[0];
    float z = out[i];
    float eff = sc + 2.0f * (2.0f * z - 1.0f);
    float aa = softplusf(eff) + 1e-6f;
    float bbk = softplusf(-eff) + 1e-6f;
    float uc = fminf(fmaxf(u[i], 1e-6f), 1.0f - 1e-6f);
    float xk = powf(1.0f - powf(1.0f - uc, 1.0f / bbk), 1.0f / aa);
    float y = -0.1f + 1.2f * xk;
    float h = (fminf(fmaxf(y, 0.0f), 1.0f) > 0.5f) ? 1.0f : 0.0f;
    out[BSv + i] = h * a_;
    if (i == 0 && out_size >= 2 * BSv + 1) out[2 * BSv] = 0.0f;
}

// ---------------- launch ---------------------------------------------------
extern "C" void kernel_launch(void* const* d_in, const int* in_sizes, int n_in,
                              void* d_out, int out_size) {
    (void)in_sizes; (void)n_in;
    const float* emb  = (const float*)d_in[0];
    const float* attn = (const float*)d_in[1];
    const float* u    = (const float*)d_in[2];
    const float* lng  = (const float*)d_in[3];
    const float* lnb  = (const float*)d_in[4];
    const float* w1   = (const float*)d_in[5];
    const float* b1   = (const float*)d_in[6];
    const float* w2   = (const float*)d_in[7];
    const float* b2   = (const float*)d_in[8];
    float* out = (float*)d_out;

    cudaFuncSetAttribute(gemm_tf32, cudaFuncAttributeMaxDynamicSharedMemorySize,
                         SMEM_BYTES);

    split_w_frag<<<(Hv * Dv) / 256, 256>>>(w1, lng);
    prep_hbias<<<Hv / 8, 256>>>(w1, lnb, b1);
    ln_stats<<<BSv / 8, 256>>>(emb, attn);
    gemm_tf32<<<dim3(NTt, BSv / BMt), 256, SMEM_BYTES>>>(emb, attn, w2);
    score_reduce<<<BSv / 256, 256>>>();
    entmax_kernel<<<Bv, 1024>>>(attn, b2, out);
    final_kernel<<<BSv / 256, 256>>>(attn, u, b2, out, out_size);
}

// round 11
// speedup vs baseline: 1.7705x; 1.7705x over previous
#include <cuda_runtime.h>
#include <cuda_fp16.h>
#include <math.h>
#include <stdint.h>

// Problem shapes (fixed by the dataset)
#define Bv   32
#define Sv   4096
#define BSv  (Bv * Sv)      // 131072 rows
#define Dv   768            // K
#define Hv   1024           // N

#define BMt  128            // CTA M tile
#define BNt  256            // CTA N tile
#define NTt  (Hv / BNt)     // 4 N-tiles
#define NCH  (Dv / 32)      // 24 k-chunks of 32

// smem layout (float indices)
#define A_BUF_F 4096        // one A buffer: 2sp x 8mblk x 2ks x 32pos x 16B
#define B_BUF_F 8192        // one B buffer: 2sp x 32nblk x 2ks x 32pos x 8B
#define OFF_B   8192
#define OFF_SHB 24576
#define OFF_SW2 24832
#define OFF_RED 25088
#define SMEM_FLOATS 26112
#define SMEM_BYTES  (SMEM_FLOATS * 4)   // 104448

// ---------------- scratch (static device globals; no allocation) ----------
__device__ float g_mu[BSv];
__device__ float g_rstd[BSv];
__device__ float g_scores[BSv];
__device__ float g_part[NTt * BSv];
// W split into 2 fp16 parts, FRAGMENT-MAJOR:
// [split][kc 24][nblk 128][ks 2][slot 32][4 halfs]  (per-split = 786432 halfs)
__device__ __align__(16) __half g_Wf[2 * 786432];
__device__ float g_hbias[Hv];

// ---------------- helpers ---------------------------------------------------
#define MMA_F16(c, a, b)                                                        \
    asm volatile("mma.sync.aligned.m16n8k16.row.col.f32.f16.f16.f32 "          \
                 "{%0,%1,%2,%3}, {%4,%5,%6,%7}, {%8,%9}, {%0,%1,%2,%3};"        \
                 : "+f"((c)[0]), "+f"((c)[1]), "+f"((c)[2]), "+f"((c)[3])       \
                 : "r"((a)[0]), "r"((a)[1]), "r"((a)[2]), "r"((a)[3]),          \
                   "r"((b)[0]), "r"((b)[1]))

__device__ __forceinline__ uint32_t pack_split_lo(float x0, float x1,
                                                  uint32_t &lo2) {
    __half h0 = __float2half_rn(x0), h1 = __float2half_rn(x1);
    __half r0 = __float2half_rn(x0 - __half2float(h0));
    __half r1 = __float2half_rn(x1 - __half2float(h1));
    lo2 = (uint32_t)__half_as_ushort(r0) | ((uint32_t)__half_as_ushort(r1) << 16);
    return (uint32_t)__half_as_ushort(h0) | ((uint32_t)__half_as_ushort(h1) << 16);
}

__device__ __forceinline__ float gelu_exact(float x) {
    return 0.5f * x * (1.0f + erff(x * 0.7071067811865475f));
}
__device__ __forceinline__ float softplusf(float x) {
    return fmaxf(x, 0.0f) + log1pf(expf(-fabsf(x)));
}

// ---------------- prep: fold ln_g into W1, fp16 split, frag-major ---------
__global__ void split_w_frag(const float* __restrict__ w1, const float* __restrict__ lng) {
    int i = blockIdx.x * 256 + threadIdx.x;     // i < Hv*Dv
    int n = i / Dv, k = i % Dv;
    float w = w1[i] * lng[k];
    __half h1 = __float2half_rn(w);
    __half h2 = __float2half_rn(w - __half2float(h1));
    int kc = k >> 5, kl = k & 31, ks = kl >> 4, kk = kl & 15;
    int tig = (kk & 7) >> 1, breg = kk >> 3, lo = kk & 1;
    int nblk = n >> 3, gg = n & 7, slot = tig * 8 + gg;
    size_t base = (((size_t)(kc * 128 + nblk)) * 2 + ks) * 128 + slot * 4 + breg * 2 + lo;
    g_Wf[base]          = h1;
    g_Wf[786432 + base] = h2;
}

__global__ void prep_hbias(const float* __restrict__ w1, const float* __restrict__ lnb,
                           const float* __restrict__ b1) {
    int h    = blockIdx.x * 8 + (threadIdx.x >> 5);
    int lane = threadIdx.x & 31;
    const float* wr = w1 + (size_t)h * Dv;
    float s = 0.0f;
    for (int d = lane; d < Dv; d += 32) s = fmaf(lnb[d], wr[d], s);
#pragma unroll
    for (int o = 16; o; o >>= 1) s += __shfl_xor_sync(0xffffffffu, s, o);
    if (lane == 0) g_hbias[h] = s + b1[h];
}

// ---------------- LayerNorm stats: one warp per row -----------------------
__global__ void ln_stats(const float* __restrict__ emb, const float* __restrict__ attn) {
    int row  = blockIdx.x * 8 + (threadIdx.x >> 5);
    int lane = threadIdx.x & 31;
    const float4* ev = (const float4*)(emb + (size_t)row * Dv);
    float at = attn[row];
    float s = 0.0f, ss = 0.0f;
#pragma unroll
    for (int j = 0; j < Dv / 128; j++) {
        float4 v = ev[lane + 32 * j];
        float a = v.x * at, b = v.y * at, c = v.z * at, d = v.w * at;
        s += a + b + c + d;
        ss = fmaf(a, a, ss); ss = fmaf(b, b, ss);
        ss = fmaf(c, c, ss); ss = fmaf(d, d, ss);
    }
#pragma unroll
    for (int o = 16; o; o >>= 1) {
        s  += __shfl_xor_sync(0xffffffffu, s,  o);
        ss += __shfl_xor_sync(0xffffffffu, ss, o);
    }
    if (lane == 0) {
        float mu  = s * (1.0f / Dv);
        float var = fmaxf(ss * (1.0f / Dv) - mu * mu, 0.0f);
        g_mu[row]   = mu;
        g_rstd[row] = 1.0f / sqrtf(var + 1e-5f);
    }
}

// ---------------- fused LN + 3xFP16 GEMM + GELU + w2-dot ------------------
// CTA 128x256, 16 warps (2x8), warp tile 64x32, mma m16n8k16 fp16,
// products A1B1 + A1B2 + A2B1 (dropped term ~2^-22).
// A: LN + fp16-split on the fly, fragment-packed 16B slots (STS.32 x8/thread).
// B: cp.async from fragment-major g_Wf (LDS.64 per fragment).

__global__ void __launch_bounds__(512, 1)
gemm_fp16(const float* __restrict__ emb, const float* __restrict__ attn,
          const float* __restrict__ w2) {
    extern __shared__ float smf[];
    uint32_t* smu = (uint32_t*)smf;
    uint32_t smemB_addr = (uint32_t)__cvta_generic_to_shared(&smf[OFF_B]);

    int nt = blockIdx.x, mt = blockIdx.y;
    int m0 = mt * BMt, n0 = nt * BNt;
    int tid = threadIdx.x;
    int lane = tid & 31, wid = tid >> 5;
    int warp_m = wid >> 3, warp_n = wid & 7;     // 2 x 8
    int g = lane >> 2, tig = lane & 3;
    int pc = tig * 8 + g;                         // fragment slot index

    if (tid < BNt) {
        smf[OFF_SHB + tid] = g_hbias[n0 + tid];
        smf[OFF_SW2 + tid] = w2[n0 + tid];
    }

    // A producer constants: thread owns (row mm, k-quad q of 8)
    int mm = tid & 127;
    int q  = tid >> 7;                            // 0..3
    int mrow = m0 + mm;
    float rsv = g_rstd[mrow];
    float sA = attn[mrow] * rsv;
    float tA = g_mu[mrow] * rsv;
    int gA = mm & 7, hiA = (mm >> 3) & 1, mblkA = mm >> 4;
    int ksA = q >> 1, c8A = q & 1;
    // A slot uint index (sp=0): abase0 + t*32 ; sp=1: +2048
    int abase0 = ((mblkA * 2 + ksA) * 32 + gA) * 4 + c8A * 2 + hiA;

    float av[8];

#define A_LOAD(KC)                                                              \
    do {                                                                        \
        const float4* ea_ = (const float4*)(emb + (size_t)mrow * Dv             \
                                            + (KC) * 32 + q * 8);               \
        float4 v0_ = ea_[0], v1_ = ea_[1];                                      \
        av[0] = v0_.x; av[1] = v0_.y; av[2] = v0_.z; av[3] = v0_.w;             \
        av[4] = v1_.x; av[5] = v1_.y; av[6] = v1_.z; av[7] = v1_.w;             \
    } while (0)

#define A_STORE(BUF)                                                            \
    do {                                                                        \
        _Pragma("unroll")                                                       \
        for (int t_ = 0; t_ < 4; t_++) {                                        \
            float x0_ = fmaf(av[2 * t_], sA, -tA);                              \
            float x1_ = fmaf(av[2 * t_ + 1], sA, -tA);                          \
            uint32_t p2_;                                                       \
            uint32_t p1_ = pack_split_lo(x0_, x1_, p2_);                        \
            int s0_ = (BUF) * A_BUF_F + abase0 + t_ * 32;                       \
            smu[s0_]        = p1_;                                              \
            smu[s0_ + 2048] = p2_;                                              \
        }                                                                       \
    } while (0)

// One B buffer = 2048 x 16B lines; 512 threads -> 4 lines per thread.
#define PRODUCE_B(KC, BUF)                                                      \
    do {                                                                        \
        _Pragma("unroll")                                                       \
        for (int i_ = 0; i_ < 4; i_++) {                                        \
            int L_ = i_ * 512 + tid;                                            \
            int j_ = L_ & 15, ks_ = (L_ >> 4) & 1;                              \
            int nbl_ = (L_ >> 5) & 31, sp_ = L_ >> 10;                          \
            size_t gidx_ = (size_t)sp_ * 786432                                 \
                + ((size_t)((KC) * 128 + nt * 32 + nbl_) * 2 + ks_) * 128       \
                + j_ * 8;                                                       \
            uint32_t sa_ = smemB_addr + (uint32_t)((BUF) * 32768 + L_ * 16);    \
            asm volatile("cp.async.cg.shared.global [%0], [%1], 16;"            \
                         :: "r"(sa_), "l"(g_Wf + gidx_) : "memory");            \
        }                                                                       \
        asm volatile("cp.async.commit_group;" ::: "memory");                    \
    } while (0)

    float acc[4][4][4];
#pragma unroll
    for (int tm = 0; tm < 4; tm++)
#pragma unroll
        for (int tn = 0; tn < 4; tn++)
#pragma unroll
            for (int e = 0; e < 4; e++) acc[tm][tn][e] = 0.0f;

    // prologue
    PRODUCE_B(0, 0);
    A_LOAD(0);
    A_STORE(0);
    asm volatile("cp.async.wait_group 0;" ::: "memory");
    __syncthreads();

    int st = 0;
#pragma unroll 1
    for (int c = 0; c < NCH; c++) {
        if (c + 1 < NCH) {
            PRODUCE_B(c + 1, st ^ 1);
            A_LOAD(c + 1);
        }

        int aoff = st * A_BUF_F;           // uint index base (A region at 0)
        int boff = OFF_B + st * B_BUF_F;   // float index base
#pragma unroll
        for (int ks = 0; ks < 2; ks++) {
            uint32_t bf[2][4][2];
#pragma unroll
            for (int sp = 0; sp < 2; sp++)
#pragma unroll
                for (int tn = 0; tn < 4; tn++) {
                    int nblk = warp_n * 4 + tn;
                    float2 bv = *(const float2*)&smf[boff
                        + (((sp * 32 + nblk) * 2 + ks) * 32 + pc) * 2];
                    bf[sp][tn][0] = __float_as_uint(bv.x);
                    bf[sp][tn][1] = __float_as_uint(bv.y);
                }
            {   // A split 1: products A1*B1 and A1*B2
                uint32_t af[4][4];
#pragma unroll
                for (int tm = 0; tm < 4; tm++) {
                    int mblk = warp_m * 4 + tm;
                    float4 avv = *(const float4*)&smf[aoff
                        + ((mblk * 2 + ks) * 32 + pc) * 4];
                    af[tm][0] = __float_as_uint(avv.x);
                    af[tm][1] = __float_as_uint(avv.y);
                    af[tm][2] = __float_as_uint(avv.z);
                    af[tm][3] = __float_as_uint(avv.w);
                }
#pragma unroll
                for (int tm = 0; tm < 4; tm++)
#pragma unroll
                    for (int tn = 0; tn < 4; tn++) {
                        MMA_F16(acc[tm][tn], af[tm], bf[0][tn]);
                        MMA_F16(acc[tm][tn], af[tm], bf[1][tn]);
                    }
            }
            {   // A split 2: product A2*B1
                uint32_t af[4][4];
#pragma unroll
                for (int tm = 0; tm < 4; tm++) {
                    int mblk = warp_m * 4 + tm;
                    float4 avv = *(const float4*)&smf[aoff + 2048
                        + ((mblk * 2 + ks) * 32 + pc) * 4];
                    af[tm][0] = __float_as_uint(avv.x);
                    af[tm][1] = __float_as_uint(avv.y);
                    af[tm][2] = __float_as_uint(avv.z);
                    af[tm][3] = __float_as_uint(avv.w);
                }
#pragma unroll
                for (int tm = 0; tm < 4; tm++)
#pragma unroll
                    for (int tn = 0; tn < 4; tn++)
                        MMA_F16(acc[tm][tn], af[tm], bf[0][tn]);
            }
        }

        if (c + 1 < NCH) A_STORE(st ^ 1);
        asm volatile("cp.async.wait_group 0;" ::: "memory");
        __syncthreads();
        st ^= 1;
    }

    // ---------------- epilogue: gelu(c + hbias) * w2, reduce ---------------
    float* shb = &smf[OFF_SHB];
    float* sw2 = &smf[OFF_SW2];
    float* red = &smf[OFF_RED];
#pragma unroll
    for (int tm = 0; tm < 4; tm++) {
        float rs0 = 0.0f, rs1 = 0.0f;
#pragma unroll
        for (int tn = 0; tn < 4; tn++) {
            int cl = warp_n * 32 + tn * 8 + 2 * tig;
            float h0 = shb[cl], h1 = shb[cl + 1];
            float w0 = sw2[cl], w1v = sw2[cl + 1];
            rs0 += gelu_exact(acc[tm][tn][0] + h0) * w0
                 + gelu_exact(acc[tm][tn][1] + h1) * w1v;
            rs1 += gelu_exact(acc[tm][tn][2] + h0) * w0
                 + gelu_exact(acc[tm][tn][3] + h1) * w1v;
        }
        rs0 += __shfl_xor_sync(0xffffffffu, rs0, 1);
        rs0 += __shfl_xor_sync(0xffffffffu, rs0, 2);
        rs1 += __shfl_xor_sync(0xffffffffu, rs1, 1);
        rs1 += __shfl_xor_sync(0xffffffffu, rs1, 2);
        if (tig == 0) {
            int r0 = warp_m * 64 + tm * 16 + g;
            red[r0 * 8 + warp_n]       = rs0;
            red[(r0 + 8) * 8 + warp_n] = rs1;
        }
    }
    __syncthreads();
    if (tid < BMt) {
        float p = 0.0f;
#pragma unroll
        for (int wnn = 0; wnn < 8; wnn++) p += red[tid * 8 + wnn];
        g_part[nt * BSv + m0 + tid] = p;
    }
}

// ---------------- fixed-order partial reduction (deterministic) -----------
__global__ void score_reduce() {
    int i = blockIdx.x * 256 + threadIdx.x;
    float s = 0.0f;
#pragma unroll
    for (int nt = 0; nt < NTt; nt++) s += g_part[nt * BSv + i];
    g_scores[i] = s;
}

// ---------------- entmax-1.5 over S via bisection on tau ------------------
__global__ void __launch_bounds__(1024)
entmax_kernel(const float* __restrict__ attn, const float* __restrict__ b2,
              float* __restrict__ zout) {
    __shared__ float sx[Sv];
    __shared__ float red[33];
    int b = blockIdx.x, tid = threadIdx.x;
    int lane = tid & 31, wid = tid >> 5;
    float b2v = b2[0];
    const float* sc = g_scores + (size_t)b * Sv;
    const float* at = attn + (size_t)b * Sv;

    float loc[4], am[4];
    float mx = -3.4e38f;
#pragma unroll
    for (int j = 0; j < 4; j++) {
        int i = tid + j * 1024;
        float a = at[i]; am[j] = a;
        float v = (a == 0.0f) ? -1e9f : sc[i] + b2v;
        v *= 0.5f;
        loc[j] = v;
        mx = fmaxf(mx, v);
    }
#pragma unroll
    for (int o = 16; o; o >>= 1) mx = fmaxf(mx, __shfl_xor_sync(0xffffffffu, mx, o));
    if (lane == 0) red[wid] = mx;
    __syncthreads();
    if (wid == 0) {
        float m = red[lane];
#pragma unroll
        for (int o = 16; o; o >>= 1) m = fmaxf(m, __shfl_xor_sync(0xffffffffu, m, o));
        if (lane == 0) red[32] = m;
    }
    __syncthreads();
    float xmax = red[32];
#pragma unroll
    for (int j = 0; j < 4; j++) sx[tid + j * 1024] = loc[j] - xmax;
    __syncthreads();

    float lo = -1.0f, hi = 0.0f;
    for (int it = 0; it < 30; it++) {
        float mid = 0.5f * (lo + hi);
        float s = 0.0f;
#pragma unroll
        for (int j = 0; j < 4; j++) {
            float d = fmaxf(sx[tid + j * 1024] - mid, 0.0f);
            s = fmaf(d, d, s);
        }
#pragma unroll
        for (int o = 16; o; o >>= 1) s += __shfl_xor_sync(0xffffffffu, s, o);
        __syncthreads();
        if (lane == 0) red[wid] = s;
        __syncthreads();
        if (wid == 0) {
            float t = red[lane];
#pragma unroll
            for (int o = 16; o; o >>= 1) t += __shfl_xor_sync(0xffffffffu, t, o);
            if (lane == 0) red[32] = t;
        }
        __syncthreads();
        float tot = red[32];
        if (tot >= 1.0f) lo = mid; else hi = mid;
    }
    float tau = 0.5f * (lo + hi);
#pragma unroll
    for (int j = 0; j < 4; j++) {
        int i = tid + j * 1024;
        float d = fmaxf(sx[i] - tau, 0.0f);
        zout[(size_t)b * Sv + i] = d * d * am[j];
    }
}

// ---------------- Kumaraswamy gate (g == h numerically) -------------------
__global__ void final_kernel(const float* __restrict__ attn, const float* __restrict__ u,
                             const float* __restrict__ b2, float* __restrict__ out,
                             int out_size) {
    int i = blockIdx.x * 256 + threadIdx.x;
    float a_ = attn[i];
    float sc = (a_ == 0.0f) ? -1e9f : g_scores[i] + b2[0];
    float z = out[i];
    float eff = sc + 2.0f * (2.0f * z - 1.0f);
    float aa = softplusf(eff) + 1e-6f;
    float bbk = softplusf(-eff) + 1e-6f;
    float uc = fminf(fmaxf(u[i], 1e-6f), 1.0f - 1e-6f);
    float xk = powf(1.0f - powf(1.0f - uc, 1.0f / bbk), 1.0f / aa);
    float y = -0.1f + 1.2f * xk;
    float h = (fminf(fmaxf(y, 0.0f), 1.0f) > 0.5f) ? 1.0f : 0.0f;
    out[BSv + i] = h * a_;
    if (i == 0 && out_size >= 2 * BSv + 1) out[2 * BSv] = 0.0f;
}

// ---------------- launch ---------------------------------------------------
extern "C" void kernel_launch(void* const* d_in, const int* in_sizes, int n_in,
                              void* d_out, int out_size) {
    (void)in_sizes; (void)n_in;
    const float* emb  = (const float*)d_in[0];
    const float* attn = (const float*)d_in[1];
    const float* u    = (const float*)d_in[2];
    const float* lng  = (const float*)d_in[3];
    const float* lnb  = (const float*)d_in[4];
    const float* w1   = (const float*)d_in[5];
    const float* b1   = (const float*)d_in[6];
    const float* w2   = (const float*)d_in[7];
    const float* b2   = (const float*)d_in[8];
    float* out = (float*)d_out;

    cudaFuncSetAttribute(gemm_fp16, cudaFuncAttributeMaxDynamicSharedMemorySize,
                         SMEM_BYTES);

    split_w_frag<<<(Hv * Dv) / 256, 256>>>(w1, lng);
    prep_hbias<<<Hv / 8, 256>>>(w1, lnb, b1);
    ln_stats<<<BSv / 8, 256>>>(emb, attn);
    gemm_fp16<<<dim3(NTt, BSv / BMt), 512, SMEM_BYTES>>>(emb, attn, w2);
    score_reduce<<<BSv / 256, 256>>>();
    entmax_kernel<<<Bv, 1024>>>(attn, b2, out);
    final_kernel<<<BSv / 256, 256>>>(attn, u, b2, out, out_size);
}

// round 12
// speedup vs baseline: 1.9152x; 1.0817x over previous
#include <cuda_runtime.h>
#include <cuda_fp16.h>
#include <math.h>
#include <stdint.h>

// Problem shapes (fixed by the dataset)
#define Bv   32
#define Sv   4096
#define BSv  (Bv * Sv)      // 131072 rows
#define Dv   768            // K
#define Hv   1024           // N

#define BMt  128            // CTA M tile
#define BNt  256            // CTA N tile
#define NTt  (Hv / BNt)     // 4 N-tiles
#define NCH  (Dv / 32)      // 24 k-chunks of 32

// smem layout (float indices)
#define A_BUF_F 4096        // one A buffer: 2sp x 8mblk x 2ks x 32slot x 16B
#define B_BUF_F 8192        // one B buffer: 32nblk x 2ks x 32slot x 16B (sp0|sp1)
#define OFF_B   8192
#define OFF_SHB 24576
#define OFF_SW2 24832
#define OFF_RED 25088
#define SMEM_FLOATS 25600
#define SMEM_BYTES  (SMEM_FLOATS * 4)   // 102400

// ---------------- scratch (static device globals; no allocation) ----------
__device__ float g_mu[BSv];
__device__ float g_rstd[BSv];
__device__ float g_scores[BSv];
__device__ float g_part[NTt * BSv];
// W split into 2 fp16 parts, FRAGMENT-MAJOR with splits interleaved per slot:
// [kc 24][nblk 128][ks 2][slot 32][sp0: 4 halfs | sp1: 4 halfs]
__device__ __align__(16) __half g_Wf[24 * 128 * 2 * 32 * 8];
__device__ float g_hbias[Hv];

// ---------------- helpers ---------------------------------------------------
#define MMA_F16(c, a, b)                                                        \
    asm volatile("mma.sync.aligned.m16n8k16.row.col.f32.f16.f16.f32 "          \
                 "{%0,%1,%2,%3}, {%4,%5,%6,%7}, {%8,%9}, {%0,%1,%2,%3};"        \
                 : "+f"((c)[0]), "+f"((c)[1]), "+f"((c)[2]), "+f"((c)[3])       \
                 : "r"((a)[0]), "r"((a)[1]), "r"((a)[2]), "r"((a)[3]),          \
                   "r"((b)[0]), "r"((b)[1]))

__device__ __forceinline__ uint32_t pack_split_lo(float x0, float x1,
                                                  uint32_t &lo2) {
    __half h0 = __float2half_rn(x0), h1 = __float2half_rn(x1);
    __half r0 = __float2half_rn(x0 - __half2float(h0));
    __half r1 = __float2half_rn(x1 - __half2float(h1));
    lo2 = (uint32_t)__half_as_ushort(r0) | ((uint32_t)__half_as_ushort(r1) << 16);
    return (uint32_t)__half_as_ushort(h0) | ((uint32_t)__half_as_ushort(h1) << 16);
}

__device__ __forceinline__ float gelu_exact(float x) {
    return 0.5f * x * (1.0f + erff(x * 0.7071067811865475f));
}
__device__ __forceinline__ float softplusf(float x) {
    return fmaxf(x, 0.0f) + log1pf(expf(-fabsf(x)));
}

// ---------------- prep: fold ln_g into W1, fp16 split, frag-major ---------
__global__ void split_w_frag(const float* __restrict__ w1, const float* __restrict__ lng) {
    int i = blockIdx.x * 256 + threadIdx.x;     // i < Hv*Dv
    int n = i / Dv, k = i % Dv;
    float w = w1[i] * lng[k];
    __half h1 = __float2half_rn(w);
    __half h2 = __float2half_rn(w - __half2float(h1));
    int kc = k >> 5, kl = k & 31, ks = kl >> 4, kk = kl & 15;
    int tig = (kk & 7) >> 1, breg = kk >> 3, lo = kk & 1;
    int nblk = n >> 3, gg = n & 7, slot = tig * 8 + gg;
    size_t base = ((((size_t)kc * 128 + nblk) * 2 + ks) * 32 + slot) * 8
                  + breg * 2 + lo;
    g_Wf[base]     = h1;   // split 0 in first 8 bytes of the slot
    g_Wf[base + 4] = h2;   // split 1 in second 8 bytes
}

__global__ void prep_hbias(const float* __restrict__ w1, const float* __restrict__ lnb,
                           const float* __restrict__ b1) {
    int h    = blockIdx.x * 8 + (threadIdx.x >> 5);
    int lane = threadIdx.x & 31;
    const float* wr = w1 + (size_t)h * Dv;
    float s = 0.0f;
    for (int d = lane; d < Dv; d += 32) s = fmaf(lnb[d], wr[d], s);
#pragma unroll
    for (int o = 16; o; o >>= 1) s += __shfl_xor_sync(0xffffffffu, s, o);
    if (lane == 0) g_hbias[h] = s + b1[h];
}

// ---------------- LayerNorm stats: one warp per row -----------------------
__global__ void ln_stats(const float* __restrict__ emb, const float* __restrict__ attn) {
    int row  = blockIdx.x * 8 + (threadIdx.x >> 5);
    int lane = threadIdx.x & 31;
    const float4* ev = (const float4*)(emb + (size_t)row * Dv);
    float at = attn[row];
    float s = 0.0f, ss = 0.0f;
#pragma unroll
    for (int j = 0; j < Dv / 128; j++) {
        float4 v = ev[lane + 32 * j];
        float a = v.x * at, b = v.y * at, c = v.z * at, d = v.w * at;
        s += a + b + c + d;
        ss = fmaf(a, a, ss); ss = fmaf(b, b, ss);
        ss = fmaf(c, c, ss); ss = fmaf(d, d, ss);
    }
#pragma unroll
    for (int o = 16; o; o >>= 1) {
        s  += __shfl_xor_sync(0xffffffffu, s,  o);
        ss += __shfl_xor_sync(0xffffffffu, ss, o);
    }
    if (lane == 0) {
        float mu  = s * (1.0f / Dv);
        float var = fmaxf(ss * (1.0f / Dv) - mu * mu, 0.0f);
        g_mu[row]   = mu;
        g_rstd[row] = 1.0f / sqrtf(var + 1e-5f);
    }
}

// ---------------- fused LN + 3xFP16 GEMM + GELU + w2-dot ------------------
// CTA 128x256, 8 warps (2x4), warp tile 64x64, mma m16n8k16 fp16,
// products A1B1 + A1B2 + A2B1 (dropped term ~2^-22).
// A: LN + fp16-split on the fly (STS.32), fragment slots of 16B.
// B: cp.async from frag-major g_Wf; one LDS.128 yields BOTH splits of a frag.

__global__ void __launch_bounds__(256, 1)
gemm_fp16(const float* __restrict__ emb, const float* __restrict__ attn,
          const float* __restrict__ w2) {
    extern __shared__ float smf[];
    uint32_t* smu = (uint32_t*)smf;
    uint32_t smemB_addr = (uint32_t)__cvta_generic_to_shared(&smf[OFF_B]);

    int nt = blockIdx.x, mt = blockIdx.y;
    int m0 = mt * BMt, n0 = nt * BNt;
    int tid = threadIdx.x;
    int lane = tid & 31, wid = tid >> 5;
    int warp_m = wid >> 2, warp_n = wid & 3;     // 2 x 4
    int g = lane >> 2, tig = lane & 3;
    int pc = tig * 8 + g;                         // fragment slot index

    if (tid < BNt) {
        smf[OFF_SHB + tid] = g_hbias[n0 + tid];
        smf[OFF_SW2 + tid] = w2[n0 + tid];
    }

    // A producer: thread owns (row mm, k-half q2 of 16)
    int mm = tid & 127;
    int q2 = tid >> 7;                            // 0..1 -> ks
    int mrow = m0 + mm;
    float rsv = g_rstd[mrow];
    float sA = attn[mrow] * rsv;
    float tA = g_mu[mrow] * rsv;
    int gA = mm & 7, hiA = (mm >> 3) & 1, mblkA = mm >> 4;

    float av[16];

#define A_LOAD(KC)                                                              \
    do {                                                                        \
        const float4* ea_ = (const float4*)(emb + (size_t)mrow * Dv             \
                                            + (KC) * 32 + q2 * 16);             \
        float4 v0_ = ea_[0], v1_ = ea_[1], v2_ = ea_[2], v3_ = ea_[3];          \
        av[0] = v0_.x;  av[1] = v0_.y;  av[2] = v0_.z;  av[3] = v0_.w;          \
        av[4] = v1_.x;  av[5] = v1_.y;  av[6] = v1_.z;  av[7] = v1_.w;          \
        av[8] = v2_.x;  av[9] = v2_.y;  av[10] = v2_.z; av[11] = v2_.w;         \
        av[12] = v3_.x; av[13] = v3_.y; av[14] = v3_.z; av[15] = v3_.w;         \
    } while (0)

#define A_STORE(BUF)                                                            \
    do {                                                                        \
        _Pragma("unroll")                                                       \
        for (int c8_ = 0; c8_ < 2; c8_++) {                                     \
            _Pragma("unroll")                                                   \
            for (int t_ = 0; t_ < 4; t_++) {                                    \
                float x0_ = fmaf(av[c8_ * 8 + 2 * t_], sA, -tA);                \
                float x1_ = fmaf(av[c8_ * 8 + 2 * t_ + 1], sA, -tA);            \
                uint32_t p2_;                                                   \
                uint32_t p1_ = pack_split_lo(x0_, x1_, p2_);                    \
                int s0_ = (BUF) * A_BUF_F                                       \
                    + ((mblkA * 2 + q2) * 32 + t_ * 8 + gA) * 4                 \
                    + c8_ * 2 + hiA;                                            \
                smu[s0_]        = p1_;                                          \
                smu[s0_ + 2048] = p2_;                                          \
            }                                                                   \
        }                                                                       \
    } while (0)

// One B buffer = 2048 x 16B lines; 256 threads -> 8 lines per thread.
#define PRODUCE_B(KC, BUF)                                                      \
    do {                                                                        \
        _Pragma("unroll")                                                       \
        for (int i_ = 0; i_ < 8; i_++) {                                        \
            int L_ = i_ * 256 + tid;                                            \
            int slot_ = L_ & 31, ks_ = (L_ >> 5) & 1, nbl_ = L_ >> 6;           \
            size_t gidx_ = ((((size_t)(KC) * 128 + nt * 32 + nbl_) * 2 + ks_)   \
                            * 32 + slot_) * 8;                                  \
            uint32_t sa_ = smemB_addr + (uint32_t)((BUF) * 32768 + L_ * 16);    \
            asm volatile("cp.async.cg.shared.global [%0], [%1], 16;"            \
                         :: "r"(sa_), "l"(g_Wf + gidx_) : "memory");            \
        }                                                                       \
        asm volatile("cp.async.commit_group;" ::: "memory");                    \
    } while (0)

    float acc[4][8][4];
#pragma unroll
    for (int tm = 0; tm < 4; tm++)
#pragma unroll
        for (int tn = 0; tn < 8; tn++)
#pragma unroll
            for (int e = 0; e < 4; e++) acc[tm][tn][e] = 0.0f;

    // prologue
    PRODUCE_B(0, 0);
    A_LOAD(0);
    A_STORE(0);
    asm volatile("cp.async.wait_group 0;" ::: "memory");
    __syncthreads();

    int st = 0;
#pragma unroll 1
    for (int c = 0; c < NCH; c++) {
        if (c + 1 < NCH) {
            PRODUCE_B(c + 1, st ^ 1);
            A_LOAD(c + 1);
        }

        int aoff = st * A_BUF_F;           // uint/float index base (A at 0)
        int boff = OFF_B + st * B_BUF_F;   // float index base
#pragma unroll
        for (int ks = 0; ks < 2; ks++) {
            // B: 8 fragments, each LDS.128 gives both splits
            uint32_t bf[2][8][2];
#pragma unroll
            for (int tn = 0; tn < 8; tn++) {
                int nblk = warp_n * 8 + tn;
                float4 bv = *(const float4*)&smf[boff
                    + ((nblk * 2 + ks) * 32 + pc) * 4];
                bf[0][tn][0] = __float_as_uint(bv.x);
                bf[0][tn][1] = __float_as_uint(bv.y);
                bf[1][tn][0] = __float_as_uint(bv.z);
                bf[1][tn][1] = __float_as_uint(bv.w);
            }
            {   // A split 1: products A1*B1 and A1*B2
                uint32_t af[4][4];
#pragma unroll
                for (int tm = 0; tm < 4; tm++) {
                    int mblk = warp_m * 4 + tm;
                    float4 avv = *(const float4*)&smf[aoff
                        + ((mblk * 2 + ks) * 32 + pc) * 4];
                    af[tm][0] = __float_as_uint(avv.x);
                    af[tm][1] = __float_as_uint(avv.y);
                    af[tm][2] = __float_as_uint(avv.z);
                    af[tm][3] = __float_as_uint(avv.w);
                }
#pragma unroll
                for (int tm = 0; tm < 4; tm++)
#pragma unroll
                    for (int tn = 0; tn < 8; tn++) {
                        MMA_F16(acc[tm][tn], af[tm], bf[0][tn]);
                        MMA_F16(acc[tm][tn], af[tm], bf[1][tn]);
                    }
            }
            {   // A split 2: product A2*B1
                uint32_t af[4][4];
#pragma unroll
                for (int tm = 0; tm < 4; tm++) {
                    int mblk = warp_m * 4 + tm;
                    float4 avv = *(const float4*)&smf[aoff + 2048
                        + ((mblk * 2 + ks) * 32 + pc) * 4];
                    af[tm][0] = __float_as_uint(avv.x);
                    af[tm][1] = __float_as_uint(avv.y);
                    af[tm][2] = __float_as_uint(avv.z);
                    af[tm][3] = __float_as_uint(avv.w);
                }
#pragma unroll
                for (int tm = 0; tm < 4; tm++)
#pragma unroll
                    for (int tn = 0; tn < 8; tn++)
                        MMA_F16(acc[tm][tn], af[tm], bf[0][tn]);
            }
        }

        if (c + 1 < NCH) A_STORE(st ^ 1);
        asm volatile("cp.async.wait_group 0;" ::: "memory");
        __syncthreads();
        st ^= 1;
    }

    // ---------------- epilogue: gelu(c + hbias) * w2, reduce ---------------
    float* shb = &smf[OFF_SHB];
    float* sw2 = &smf[OFF_SW2];
    float* red = &smf[OFF_RED];
#pragma unroll
    for (int tm = 0; tm < 4; tm++) {
        float rs0 = 0.0f, rs1 = 0.0f;
#pragma unroll
        for (int tn = 0; tn < 8; tn++) {
            int cl = warp_n * 64 + tn * 8 + 2 * tig;
            float h0 = shb[cl], h1 = shb[cl + 1];
            float w0 = sw2[cl], w1v = sw2[cl + 1];
            rs0 += gelu_exact(acc[tm][tn][0] + h0) * w0
                 + gelu_exact(acc[tm][tn][1] + h1) * w1v;
            rs1 += gelu_exact(acc[tm][tn][2] + h0) * w0
                 + gelu_exact(acc[tm][tn][3] + h1) * w1v;
        }
        rs0 += __shfl_xor_sync(0xffffffffu, rs0, 1);
        rs0 += __shfl_xor_sync(0xffffffffu, rs0, 2);
        rs1 += __shfl_xor_sync(0xffffffffu, rs1, 1);
        rs1 += __shfl_xor_sync(0xffffffffu, rs1, 2);
        if (tig == 0) {
            int r0 = warp_m * 64 + tm * 16 + g;
            red[r0 * 4 + warp_n]       = rs0;
            red[(r0 + 8) * 4 + warp_n] = rs1;
        }
    }
    __syncthreads();
    if (tid < BMt) {
        float p = red[tid * 4] + red[tid * 4 + 1]
                + red[tid * 4 + 2] + red[tid * 4 + 3];
        g_part[nt * BSv + m0 + tid] = p;
    }
}

// ---------------- fixed-order partial reduction (deterministic) -----------
__global__ void score_reduce() {
    int i = blockIdx.x * 256 + threadIdx.x;
    float s = 0.0f;
#pragma unroll
    for (int nt = 0; nt < NTt; nt++) s += g_part[nt * BSv + i];
    g_scores[i] = s;
}

// ---------------- entmax-1.5 over S via bisection on tau ------------------
__global__ void __launch_bounds__(1024)
entmax_kernel(const float* __restrict__ attn, const float* __restrict__ b2,
              float* __restrict__ zout) {
    __shared__ float sx[Sv];
    __shared__ float red[33];
    int b = blockIdx.x, tid = threadIdx.x;
    int lane = tid & 31, wid = tid >> 5;
    float b2v = b2[0];
    const float* sc = g_scores + (size_t)b * Sv;
    const float* at = attn + (size_t)b * Sv;

    float loc[4], am[4];
    float mx = -3.4e38f;
#pragma unroll
    for (int j = 0; j < 4; j++) {
        int i = tid + j * 1024;
        float a = at[i]; am[j] = a;
        float v = (a == 0.0f) ? -1e9f : sc[i] + b2v;
        v *= 0.5f;
        loc[j] = v;
        mx = fmaxf(mx, v);
    }
#pragma unroll
    for (int o = 16; o; o >>= 1) mx = fmaxf(mx, __shfl_xor_sync(0xffffffffu, mx, o));
    if (lane == 0) red[wid] = mx;
    __syncthreads();
    if (wid == 0) {
        float m = red[lane];
#pragma unroll
        for (int o = 16; o; o >>= 1) m = fmaxf(m, __shfl_xor_sync(0xffffffffu, m, o));
        if (lane == 0) red[32] = m;
    }
    __syncthreads();
    float xmax = red[32];
#pragma unroll
    for (int j = 0; j < 4; j++) sx[tid + j * 1024] = loc[j] - xmax;
    __syncthreads();

    float lo = -1.0f, hi = 0.0f;
    for (int it = 0; it < 30; it++) {
        float mid = 0.5f * (lo + hi);
        float s = 0.0f;
#pragma unroll
        for (int j = 0; j < 4; j++) {
            float d = fmaxf(sx[tid + j * 1024] - mid, 0.0f);
            s = fmaf(d, d, s);
        }
#pragma unroll
        for (int o = 16; o; o >>= 1) s += __shfl_xor_sync(0xffffffffu, s, o);
        __syncthreads();
        if (lane == 0) red[wid] = s;
        __syncthreads();
        if (wid == 0) {
            float t = red[lane];
#pragma unroll
            for (int o = 16; o; o >>= 1) t += __shfl_xor_sync(0xffffffffu, t, o);
            if (lane == 0) red[32] = t;
        }
        __syncthreads();
        float tot = red[32];
        if (tot >= 1.0f) lo = mid; else hi = mid;
    }
    float tau = 0.5f * (lo + hi);
#pragma unroll
    for (int j = 0; j < 4; j++) {
        int i = tid + j * 1024;
        float d = fmaxf(sx[i] - tau, 0.0f);
        zout[(size_t)b * Sv + i] = d * d * am[j];
    }
}

// ---------------- Kumaraswamy gate (g == h numerically) -------------------
__global__ void final_kernel(const float* __restrict__ attn, const float* __restrict__ u,
                             const float* __restrict__ b2, float* __restrict__ out,
                             int out_size) {
    int i = blockIdx.x * 256 + threadIdx.x;
    float a_ = attn[i];
    float sc = (a_ == 0.0f) ? -1e9f : g_scores[i] + b2[0];
    float z = out[i];
    float eff = sc + 2.0f * (2.0f * z - 1.0f);
    float aa = softplusf(eff) + 1e-6f;
    float bbk = softplusf(-eff) + 1e-6f;
    float uc = fminf(fmaxf(u[i], 1e-6f), 1.0f - 1e-6f);
    float xk = powf(1.0f - powf(1.0f - uc, 1.0f / bbk), 1.0f / aa);
    float y = -0.1f + 1.2f * xk;
    float h = (fminf(fmaxf(y, 0.0f), 1.0f) > 0.5f) ? 1.0f : 0.0f;
    out[BSv + i] = h * a_;
    if (i == 0 && out_size >= 2 * BSv + 1) out[2 * BSv] = 0.0f;
}

// ---------------- launch ---------------------------------------------------
extern "C" void kernel_launch(void* const* d_in, const int* in_sizes, int n_in,
                              void* d_out, int out_size) {
    (void)in_sizes; (void)n_in;
    const float* emb  = (const float*)d_in[0];
    const float* attn = (const float*)d_in[1];
    const float* u    = (const float*)d_in[2];
    const float* lng  = (const float*)d_in[3];
    const float* lnb  = (const float*)d_in[4];
    const float* w1   = (const float*)d_in[5];
    const float* b1   = (const float*)d_in[6];
    const float* w2   = (const float*)d_in[7];
    const float* b2   = (const float*)d_in[8];
    float* out = (float*)d_out;

    cudaFuncSetAttribute(gemm_fp16, cudaFuncAttributeMaxDynamicSharedMemorySize,
                         SMEM_BYTES);

    split_w_frag<<<(Hv * Dv) / 256, 256>>>(w1, lng);
    prep_hbias<<<Hv / 8, 256>>>(w1, lnb, b1);
    ln_stats<<<BSv / 8, 256>>>(emb, attn);
    gemm_fp16<<<dim3(NTt, BSv / BMt), 256, SMEM_BYTES>>>(emb, attn, w2);
    score_reduce<<<BSv / 256, 256>>>();
    entmax_kernel<<<Bv, 1024>>>(attn, b2, out);
    final_kernel<<<BSv / 256, 256>>>(attn, u, b2, out, out_size);
}

// round 13
// speedup vs baseline: 2.2962x; 1.1989x over previous
#include <cuda_runtime.h>
#include <cuda_fp16.h>
#include <math.h>
#include <stdint.h>

// Problem shapes (fixed by the dataset)
#define Bv   32
#define Sv   4096
#define BSv  (Bv * Sv)      // 131072 rows
#define Dv   768            // K
#define Hv   1024           // N

#define BMt  128            // CTA M tile
#define BNt  256            // CTA N tile
#define NTt  (Hv / BNt)     // 4 N-tiles
#define NCH  (Dv / 32)      // 24 k-chunks of 32
#define NMT  (BSv / BMt)    // 1024 M tiles

// smem layout (float indices)
#define A_BUF_F 4096        // one A buffer: 2sp x 8mblk x 2ks x 32slot x 16B
#define B_BUF_F 8192        // one B buffer: 32nblk x 2ks x 32slot x 16B (sp0|sp1)
#define OFF_B   8192
#define OFF_SHB 24576
#define OFF_SW2 24832
#define OFF_RED 25088
#define SMEM_FLOATS 25600
#define SMEM_BYTES  (SMEM_FLOATS * 4)   // 102400

// ---------------- scratch (static device globals; no allocation) ----------
__device__ float g_mu[BSv];
__device__ float g_rstd[BSv];
__device__ float g_scores[BSv];
__device__ float g_part[NTt * BSv];
// W split into 2 fp16 parts, FRAGMENT-MAJOR, splits interleaved per 16B slot:
// [kc 24][nblk 128][ks 2][slot 32][sp0: 4 halfs | sp1: 4 halfs]
__device__ __align__(16) __half g_Wf[24 * 128 * 2 * 32 * 8];
// A (LN-normalized, 2-way fp16 split), FRAGMENT-MAJOR per (mtile, kc):
// [mtile 1024][kc 24][16KB fragment buffer (1024 x uint4)]
__device__ uint4 g_Af[(size_t)NMT * NCH * 1024];   // 402MB
__device__ float g_hbias[Hv];

// ---------------- helpers ---------------------------------------------------
#define MMA_F16(c, a, b)                                                        \
    asm volatile("mma.sync.aligned.m16n8k16.row.col.f32.f16.f16.f32 "          \
                 "{%0,%1,%2,%3}, {%4,%5,%6,%7}, {%8,%9}, {%0,%1,%2,%3};"        \
                 : "+f"((c)[0]), "+f"((c)[1]), "+f"((c)[2]), "+f"((c)[3])       \
                 : "r"((a)[0]), "r"((a)[1]), "r"((a)[2]), "r"((a)[3]),          \
                   "r"((b)[0]), "r"((b)[1]))

__device__ __forceinline__ uint32_t pack_split_lo(float x0, float x1,
                                                  uint32_t &lo2) {
    __half h0 = __float2half_rn(x0), h1 = __float2half_rn(x1);
    __half r0 = __float2half_rn(x0 - __half2float(h0));
    __half r1 = __float2half_rn(x1 - __half2float(h1));
    lo2 = (uint32_t)__half_as_ushort(r0) | ((uint32_t)__half_as_ushort(r1) << 16);
    return (uint32_t)__half_as_ushort(h0) | ((uint32_t)__half_as_ushort(h1) << 16);
}

__device__ __forceinline__ float gelu_exact(float x) {
    return 0.5f * x * (1.0f + erff(x * 0.7071067811865475f));
}
__device__ __forceinline__ float softplusf(float x) {
    return fmaxf(x, 0.0f) + log1pf(expf(-fabsf(x)));
}

// ---------------- prep: fold ln_g into W1, fp16 split, frag-major ---------
__global__ void split_w_frag(const float* __restrict__ w1, const float* __restrict__ lng) {
    int i = blockIdx.x * 256 + threadIdx.x;     // i < Hv*Dv
    int n = i / Dv, k = i % Dv;
    float w = w1[i] * lng[k];
    __half h1 = __float2half_rn(w);
    __half h2 = __float2half_rn(w - __half2float(h1));
    int kc = k >> 5, kl = k & 31, ks = kl >> 4, kk = kl & 15;
    int tig = (kk & 7) >> 1, breg = kk >> 3, lo = kk & 1;
    int nblk = n >> 3, gg = n & 7, slot = tig * 8 + gg;
    size_t base = ((((size_t)kc * 128 + nblk) * 2 + ks) * 32 + slot) * 8
                  + breg * 2 + lo;
    g_Wf[base]     = h1;
    g_Wf[base + 4] = h2;
}

__global__ void prep_hbias(const float* __restrict__ w1, const float* __restrict__ lnb,
                           const float* __restrict__ b1) {
    int h    = blockIdx.x * 8 + (threadIdx.x >> 5);
    int lane = threadIdx.x & 31;
    const float* wr = w1 + (size_t)h * Dv;
    float s = 0.0f;
    for (int d = lane; d < Dv; d += 32) s = fmaf(lnb[d], wr[d], s);
#pragma unroll
    for (int o = 16; o; o >>= 1) s += __shfl_xor_sync(0xffffffffu, s, o);
    if (lane == 0) g_hbias[h] = s + b1[h];
}

// ---------------- LayerNorm stats: one warp per row -----------------------
__global__ void ln_stats(const float* __restrict__ emb, const float* __restrict__ attn) {
    int row  = blockIdx.x * 8 + (threadIdx.x >> 5);
    int lane = threadIdx.x & 31;
    const float4* ev = (const float4*)(emb + (size_t)row * Dv);
    float at = attn[row];
    float s = 0.0f, ss = 0.0f;
#pragma unroll
    for (int j = 0; j < Dv / 128; j++) {
        float4 v = ev[lane + 32 * j];
        float a = v.x * at, b = v.y * at, c = v.z * at, d = v.w * at;
        s += a + b + c + d;
        ss = fmaf(a, a, ss); ss = fmaf(b, b, ss);
        ss = fmaf(c, c, ss); ss = fmaf(d, d, ss);
    }
#pragma unroll
    for (int o = 16; o; o >>= 1) {
        s  += __shfl_xor_sync(0xffffffffu, s,  o);
        ss += __shfl_xor_sync(0xffffffffu, ss, o);
    }
    if (lane == 0) {
        float mu  = s * (1.0f / Dv);
        float var = fmaxf(ss * (1.0f / Dv) - mu * mu, 0.0f);
        g_mu[row]   = mu;
        g_rstd[row] = 1.0f / sqrtf(var + 1e-5f);
    }
}

// ---------------- prep: LN + fp16 split of A, fragment-major global -------
// Block 256 = (mm 128, q2 2) handles one (mtile, kc); stages the 16KB
// fragment buffer in smem, then writes it out fully coalesced.
__global__ void __launch_bounds__(256) ln_split_a(const float* __restrict__ emb,
                                                  const float* __restrict__ attn) {
    __shared__ uint32_t sbuf[4096];
    int kc = blockIdx.x, mtile = blockIdx.y;
    int tid = threadIdx.x;
    int mm = tid & 127, q2 = tid >> 7;
    int mrow = mtile * BMt + mm;
    float rsv = g_rstd[mrow];
    float sA = attn[mrow] * rsv;
    float tA = g_mu[mrow] * rsv;
    int gA = mm & 7, hiA = (mm >> 3) & 1, mblkA = mm >> 4;

    const float4* ea = (const float4*)(emb + (size_t)mrow * Dv + kc * 32 + q2 * 16);
    float4 v0 = ea[0], v1 = ea[1], v2 = ea[2], v3 = ea[3];
    float av[16] = {v0.x, v0.y, v0.z, v0.w, v1.x, v1.y, v1.z, v1.w,
                    v2.x, v2.y, v2.z, v2.w, v3.x, v3.y, v3.z, v3.w};
#pragma unroll
    for (int c8 = 0; c8 < 2; c8++) {
#pragma unroll
        for (int t = 0; t < 4; t++) {
            float x0 = fmaf(av[c8 * 8 + 2 * t], sA, -tA);
            float x1 = fmaf(av[c8 * 8 + 2 * t + 1], sA, -tA);
            uint32_t p2;
            uint32_t p1 = pack_split_lo(x0, x1, p2);
            int s0 = ((mblkA * 2 + q2) * 32 + t * 8 + gA) * 4 + c8 * 2 + hiA;
            sbuf[s0]        = p1;
            sbuf[s0 + 2048] = p2;
        }
    }
    __syncthreads();
    const uint4* sb4 = (const uint4*)sbuf;
    uint4* dst = g_Af + ((size_t)mtile * NCH + kc) * 1024;
#pragma unroll
    for (int i = 0; i < 4; i++) dst[tid + i * 256] = sb4[tid + i * 256];
}

// ---------------- 3xFP16 GEMM + GELU + w2-dot ------------------------------
// CTA 128x256, 8 warps (2x4), warp tile 64x64, mma m16n8k16,
// products A1B1 + A1B2 + A2B1. Both A and B stream in via cp.async from
// fragment-major global; consumer is pure LDS.128 + HMMA.

__global__ void __launch_bounds__(256, 1)
gemm_fp16(const float* __restrict__ w2) {
    extern __shared__ float smf[];
    uint32_t smemA_addr = (uint32_t)__cvta_generic_to_shared(&smf[0]);
    uint32_t smemB_addr = (uint32_t)__cvta_generic_to_shared(&smf[OFF_B]);

    int nt = blockIdx.x, mt = blockIdx.y;
    int n0 = nt * BNt;
    int tid = threadIdx.x;
    int lane = tid & 31, wid = tid >> 5;
    int warp_m = wid >> 2, warp_n = wid & 3;     // 2 x 4
    int g = lane >> 2, tig = lane & 3;
    int pc = tig * 8 + g;                         // fragment slot index

    if (tid < BNt) {
        smf[OFF_SHB + tid] = g_hbias[n0 + tid];
        smf[OFF_SW2 + tid] = w2[n0 + tid];
    }

    const uint4* aBase = g_Af + (size_t)mt * NCH * 1024;

// A: 1024 lines (4/thread). B: 2048 lines (8/thread). One commit group.
#define PRODUCE(KC, BUF)                                                        \
    do {                                                                        \
        const uint4* asrc_ = aBase + (KC) * 1024;                               \
        _Pragma("unroll")                                                       \
        for (int i_ = 0; i_ < 4; i_++) {                                        \
            int L_ = i_ * 256 + tid;                                            \
            uint32_t sa_ = smemA_addr + (uint32_t)((BUF) * 16384 + L_ * 16);    \
            asm volatile("cp.async.cg.shared.global [%0], [%1], 16;"            \
                         :: "r"(sa_), "l"(asrc_ + L_) : "memory");              \
        }                                                                       \
        _Pragma("unroll")                                                       \
        for (int i_ = 0; i_ < 8; i_++) {                                        \
            int L_ = i_ * 256 + tid;                                            \
            int slot_ = L_ & 31, ks_ = (L_ >> 5) & 1, nbl_ = L_ >> 6;           \
            size_t gidx_ = ((((size_t)(KC) * 128 + nt * 32 + nbl_) * 2 + ks_)   \
                            * 32 + slot_) * 8;                                  \
            uint32_t sb_ = smemB_addr + (uint32_t)((BUF) * 32768 + L_ * 16);    \
            asm volatile("cp.async.cg.shared.global [%0], [%1], 16;"            \
                         :: "r"(sb_), "l"(g_Wf + gidx_) : "memory");            \
        }                                                                       \
        asm volatile("cp.async.commit_group;" ::: "memory");                    \
    } while (0)

    float acc[4][8][4];
#pragma unroll
    for (int tm = 0; tm < 4; tm++)
#pragma unroll
        for (int tn = 0; tn < 8; tn++)
#pragma unroll
            for (int e = 0; e < 4; e++) acc[tm][tn][e] = 0.0f;

    PRODUCE(0, 0);
    asm volatile("cp.async.wait_group 0;" ::: "memory");
    __syncthreads();

    int st = 0;
#pragma unroll 1
    for (int c = 0; c < NCH; c++) {
        if (c + 1 < NCH) PRODUCE(c + 1, st ^ 1);

        int aoff = st * A_BUF_F;           // float index base (A at 0)
        int boff = OFF_B + st * B_BUF_F;
#pragma unroll
        for (int ks = 0; ks < 2; ks++) {
            uint32_t af1[4][4], af2[4][4];
#pragma unroll
            for (int tm = 0; tm < 4; tm++) {
                int mblk = warp_m * 4 + tm;
                float4 v1 = *(const float4*)&smf[aoff
                    + ((mblk * 2 + ks) * 32 + pc) * 4];
                af1[tm][0] = __float_as_uint(v1.x);
                af1[tm][1] = __float_as_uint(v1.y);
                af1[tm][2] = __float_as_uint(v1.z);
                af1[tm][3] = __float_as_uint(v1.w);
                float4 v2 = *(const float4*)&smf[aoff + 2048
                    + ((mblk * 2 + ks) * 32 + pc) * 4];
                af2[tm][0] = __float_as_uint(v2.x);
                af2[tm][1] = __float_as_uint(v2.y);
                af2[tm][2] = __float_as_uint(v2.z);
                af2[tm][3] = __float_as_uint(v2.w);
            }
#pragma unroll
            for (int h = 0; h < 2; h++) {
                uint32_t bf[2][4][2];
#pragma unroll
                for (int tn = 0; tn < 4; tn++) {
                    int nblk = warp_n * 8 + h * 4 + tn;
                    float4 bv = *(const float4*)&smf[boff
                        + ((nblk * 2 + ks) * 32 + pc) * 4];
                    bf[0][tn][0] = __float_as_uint(bv.x);
                    bf[0][tn][1] = __float_as_uint(bv.y);
                    bf[1][tn][0] = __float_as_uint(bv.z);
                    bf[1][tn][1] = __float_as_uint(bv.w);
                }
#pragma unroll
                for (int tm = 0; tm < 4; tm++)
#pragma unroll
                    for (int tn = 0; tn < 4; tn++) {
                        MMA_F16(acc[tm][h * 4 + tn], af1[tm], bf[0][tn]);
                        MMA_F16(acc[tm][h * 4 + tn], af1[tm], bf[1][tn]);
                        MMA_F16(acc[tm][h * 4 + tn], af2[tm], bf[0][tn]);
                    }
            }
        }

        asm volatile("cp.async.wait_group 0;" ::: "memory");
        __syncthreads();
        st ^= 1;
    }

    // ---------------- epilogue: gelu(c + hbias) * w2, reduce ---------------
    float* shb = &smf[OFF_SHB];
    float* sw2 = &smf[OFF_SW2];
    float* red = &smf[OFF_RED];
#pragma unroll
    for (int tm = 0; tm < 4; tm++) {
        float rs0 = 0.0f, rs1 = 0.0f;
#pragma unroll
        for (int tn = 0; tn < 8; tn++) {
            int cl = warp_n * 64 + tn * 8 + 2 * tig;
            float h0 = shb[cl], h1 = shb[cl + 1];
            float w0 = sw2[cl], w1v = sw2[cl + 1];
            rs0 += gelu_exact(acc[tm][tn][0] + h0) * w0
                 + gelu_exact(acc[tm][tn][1] + h1) * w1v;
            rs1 += gelu_exact(acc[tm][tn][2] + h0) * w0
                 + gelu_exact(acc[tm][tn][3] + h1) * w1v;
        }
        rs0 += __shfl_xor_sync(0xffffffffu, rs0, 1);
        rs0 += __shfl_xor_sync(0xffffffffu, rs0, 2);
        rs1 += __shfl_xor_sync(0xffffffffu, rs1, 1);
        rs1 += __shfl_xor_sync(0xffffffffu, rs1, 2);
        if (tig == 0) {
            int r0 = warp_m * 64 + tm * 16 + g;
            red[r0 * 4 + warp_n]       = rs0;
            red[(r0 + 8) * 4 + warp_n] = rs1;
        }
    }
    __syncthreads();
    if (tid < BMt) {
        float p = red[tid * 4] + red[tid * 4 + 1]
                + red[tid * 4 + 2] + red[tid * 4 + 3];
        g_part[nt * BSv + mt * BMt + tid] = p;
    }
}

// ---------------- fixed-order partial reduction (deterministic) -----------
__global__ void score_reduce() {
    int i = blockIdx.x * 256 + threadIdx.x;
    float s = 0.0f;
#pragma unroll
    for (int nt = 0; nt < NTt; nt++) s += g_part[nt * BSv + i];
    g_scores[i] = s;
}

// ---------------- entmax-1.5 over S via bisection on tau ------------------
__global__ void __launch_bounds__(1024)
entmax_kernel(const float* __restrict__ attn, const float* __restrict__ b2,
              float* __restrict__ zout) {
    __shared__ float sx[Sv];
    __shared__ float red[33];
    int b = blockIdx.x, tid = threadIdx.x;
    int lane = tid & 31, wid = tid >> 5;
    float b2v = b2[0];
    const float* sc = g_scores + (size_t)b * Sv;
    const float* at = attn + (size_t)b * Sv;

    float loc[4], am[4];
    float mx = -3.4e38f;
#pragma unroll
    for (int j = 0; j < 4; j++) {
        int i = tid + j * 1024;
        float a = at[i]; am[j] = a;
        float v = (a == 0.0f) ? -1e9f : sc[i] + b2v;
        v *= 0.5f;
        loc[j] = v;
        mx = fmaxf(mx, v);
    }
#pragma unroll
    for (int o = 16; o; o >>= 1) mx = fmaxf(mx, __shfl_xor_sync(0xffffffffu, mx, o));
    if (lane == 0) red[wid] = mx;
    __syncthreads();
    if (wid == 0) {
        float m = red[lane];
#pragma unroll
        for (int o = 16; o; o >>= 1) m = fmaxf(m, __shfl_xor_sync(0xffffffffu, m, o));
        if (lane == 0) red[32] = m;
    }
    __syncthreads();
    float xmax = red[32];
#pragma unroll
    for (int j = 0; j < 4; j++) sx[tid + j * 1024] = loc[j] - xmax;
    __syncthreads();

    float lo = -1.0f, hi = 0.0f;
    for (int it = 0; it < 30; it++) {
        float mid = 0.5f * (lo + hi);
        float s = 0.0f;
#pragma unroll
        for (int j = 0; j < 4; j++) {
            float d = fmaxf(sx[tid + j * 1024] - mid, 0.0f);
            s = fmaf(d, d, s);
        }
#pragma unroll
        for (int o = 16; o; o >>= 1) s += __shfl_xor_sync(0xffffffffu, s, o);
        __syncthreads();
        if (lane == 0) red[wid] = s;
        __syncthreads();
        if (wid == 0) {
            float t = red[lane];
#pragma unroll
            for (int o = 16; o; o >>= 1) t += __shfl_xor_sync(0xffffffffu, t, o);
            if (lane == 0) red[32] = t;
        }
        __syncthreads();
        float tot = red[32];
        if (tot >= 1.0f) lo = mid; else hi = mid;
    }
    float tau = 0.5f * (lo + hi);
#pragma unroll
    for (int j = 0; j < 4; j++) {
        int i = tid + j * 1024;
        float d = fmaxf(sx[i] - tau, 0.0f);
        zout[(size_t)b * Sv + i] = d * d * am[j];
    }
}

// ---------------- Kumaraswamy gate (g == h numerically) -------------------
__global__ void final_kernel(const float* __restrict__ attn, const float* __restrict__ u,
                             const float* __restrict__ b2, float* __restrict__ out,
                             int out_size) {
    int i = blockIdx.x * 256 + threadIdx.x;
    float a_ = attn[i];
    float sc = (a_ == 0.0f) ? -1e9f : g_scores[i] + b2[0];
    float z = out[i];
    float eff = sc + 2.0f * (2.0f * z - 1.0f);
    float aa = softplusf(eff) + 1e-6f;
    float bbk = softplusf(-eff) + 1e-6f;
    float uc = fminf(fmaxf(u[i], 1e-6f), 1.0f - 1e-6f);
    float xk = powf(1.0f - powf(1.0f - uc, 1.0f / bbk), 1.0f / aa);
    float y = -0.1f + 1.2f * xk;
    float h = (fminf(fmaxf(y, 0.0f), 1.0f) > 0.5f) ? 1.0f : 0.0f;
    out[BSv + i] = h * a_;
    if (i == 0 && out_size >= 2 * BSv + 1) out[2 * BSv] = 0.0f;
}

// ---------------- launch ---------------------------------------------------
extern "C" void kernel_launch(void* const* d_in, const int* in_sizes, int n_in,
                              void* d_out, int out_size) {
    (void)in_sizes; (void)n_in;
    const float* emb  = (const float*)d_in[0];
    const float* attn = (const float*)d_in[1];
    const float* u    = (const float*)d_in[2];
    const float* lng  = (const float*)d_in[3];
    const float* lnb  = (const float*)d_in[4];
    const float* w1   = (const float*)d_in[5];
    const float* b1   = (const float*)d_in[6];
    const float* w2   = (const float*)d_in[7];
    const float* b2   = (const float*)d_in[8];
    float* out = (float*)d_out;

    cudaFuncSetAttribute(gemm_fp16, cudaFuncAttributeMaxDynamicSharedMemorySize,
                         SMEM_BYTES);

    split_w_frag<<<(Hv * Dv) / 256, 256>>>(w1, lng);
    prep_hbias<<<Hv / 8, 256>>>(w1, lnb, b1);
    ln_stats<<<BSv / 8, 256>>>(emb, attn);
    ln_split_a<<<dim3(NCH, NMT), 256>>>(emb, attn);
    gemm_fp16<<<dim3(NTt, NMT), 256, SMEM_BYTES>>>(w2);
    score_reduce<<<BSv / 256, 256>>>();
    entmax_kernel<<<Bv, 1024>>>(attn, b2, out);
    final_kernel<<<BSv / 256, 256>>>(attn, u, b2, out, out_size);
}